// round 8
// baseline (speedup 1.0000x reference)
#include <cuda_runtime.h>
#include <cuda_bf16.h>
#include <math.h>
#include <stdint.h>

// Problem constants (fixed by setup_inputs)
#define BSZ    2
#define LSEQ   1024
#define HDIM   2048
#define DDIM   4096
#define NSTATE 16
#define RRANK  128
#define KCONV  4
#define BL     (BSZ * LSEQ)          // 2048 rows
#define P2D    (2 * DDIM)            // 8192
#define SP_W   (RRANK + 2 * NSTATE)  // 160
#define XP_SPLIT 8                   // split-K factor for x_proj
#define XP_KLEN  (DDIM / XP_SPLIT)   // 512

// ---------------------------------------------------------------------------
// Scratch: static device globals (no cudaMalloc allowed)
// ---------------------------------------------------------------------------
__device__ float g_proj[(size_t)BL * P2D];     // in_proj output [BL, 8192] (u | gate)
__device__ float g_sp  [(size_t)BL * SP_W];    // x_proj output [BL, 160]
__device__ float g_dt  [(size_t)BL * DDIM];    // softplus(dt_proj) [BL, D]
__device__ float g_xpp [(size_t)XP_SPLIT * BL * SP_W];  // split-K partials

// bf16 hi/lo split buffers
__device__ __nv_bfloat16 g_hs_h[(size_t)BL * HDIM],  g_hs_l[(size_t)BL * HDIM];
__device__ __nv_bfloat16 g_win_h[(size_t)P2D * HDIM], g_win_l[(size_t)P2D * HDIM];
__device__ __nv_bfloat16 g_u_h[(size_t)BL * DDIM],   g_u_l[(size_t)BL * DDIM];
__device__ __nv_bfloat16 g_wx_h[(size_t)SP_W * DDIM], g_wx_l[(size_t)SP_W * DDIM];
__device__ __nv_bfloat16 g_sp_h[(size_t)BL * SP_W],  g_sp_l[(size_t)BL * SP_W];
__device__ __nv_bfloat16 g_wdt_h[(size_t)DDIM * RRANK], g_wdt_l[(size_t)DDIM * RRANK];
__device__ __nv_bfloat16 g_y_h[(size_t)BL * DDIM],   g_y_l[(size_t)BL * DDIM];
__device__ __nv_bfloat16 g_wo_h[(size_t)HDIM * DDIM], g_wo_l[(size_t)HDIM * DDIM];

__device__ __forceinline__ float softplusf(float x) {
    return (x > 20.f) ? x : log1pf(__expf(x));
}
__device__ __forceinline__ float siluf(float x) {
    return x / (1.f + __expf(-x));
}

// ---------------------------------------------------------------------------
// PTX helpers (sm_80+ portable: cp.async / ldmatrix / mma.sync)
// ---------------------------------------------------------------------------
__device__ __forceinline__ uint32_t smem_u32(const void* p) {
    uint32_t a;
    asm("{ .reg .u64 t; cvta.to.shared.u64 t, %1; cvt.u32.u64 %0, t; }" : "=r"(a) : "l"(p));
    return a;
}
__device__ __forceinline__ void cpa16(uint32_t dst, const void* src, int sz) {
    asm volatile("cp.async.cg.shared.global [%0], [%1], 16, %2;"
                 :: "r"(dst), "l"(src), "r"(sz) : "memory");
}
__device__ __forceinline__ void cpa16f(uint32_t dst, const void* src) {
    asm volatile("cp.async.cg.shared.global [%0], [%1], 16;"
                 :: "r"(dst), "l"(src) : "memory");
}
__device__ __forceinline__ void cpa_commit() {
    asm volatile("cp.async.commit_group;" ::: "memory");
}
template <int N>
__device__ __forceinline__ void cpa_wait() {
    asm volatile("cp.async.wait_group %0;" :: "n"(N) : "memory");
}
__device__ __forceinline__ void ldsm_x4(uint32_t* r, uint32_t addr) {
    asm volatile("ldmatrix.sync.aligned.m8n8.x4.shared.b16 {%0,%1,%2,%3}, [%4];"
                 : "=r"(r[0]), "=r"(r[1]), "=r"(r[2]), "=r"(r[3]) : "r"(addr));
}
__device__ __forceinline__ void mma_bf16(float* c, const uint32_t* a, const uint32_t* b) {
    asm volatile(
        "mma.sync.aligned.m16n8k16.row.col.f32.bf16.bf16.f32 "
        "{%0,%1,%2,%3}, {%4,%5,%6,%7}, {%8,%9}, {%0,%1,%2,%3};"
        : "+f"(c[0]), "+f"(c[1]), "+f"(c[2]), "+f"(c[3])
        : "r"(a[0]), "r"(a[1]), "r"(a[2]), "r"(a[3]), "r"(b[0]), "r"(b[1]));
}

// ---------------------------------------------------------------------------
// Merged fp32 -> bf16 hi/lo split for all 5 weight/input tensors (1 launch)
// ---------------------------------------------------------------------------
#define CVT_N0 (BL * HDIM / 4)
#define CVT_N1 (CVT_N0 + P2D * HDIM / 4)
#define CVT_N2 (CVT_N1 + SP_W * DDIM / 4)
#define CVT_N3 (CVT_N2 + DDIM * RRANK / 4)
#define CVT_N4 (CVT_N3 + HDIM * DDIM / 4)

__device__ __forceinline__ void cvt_one(const float* __restrict__ x,
                                        __nv_bfloat16* __restrict__ h,
                                        __nv_bfloat16* __restrict__ l, int i)
{
    float4 v = ((const float4*)x)[i];
    __nv_bfloat162 h0 = __floats2bfloat162_rn(v.x, v.y);
    __nv_bfloat162 h1 = __floats2bfloat162_rn(v.z, v.w);
    __nv_bfloat162 l0 = __floats2bfloat162_rn(v.x - __low2float(h0), v.y - __high2float(h0));
    __nv_bfloat162 l1 = __floats2bfloat162_rn(v.z - __low2float(h1), v.w - __high2float(h1));
    ((__nv_bfloat162*)h)[2 * i]     = h0;
    ((__nv_bfloat162*)h)[2 * i + 1] = h1;
    ((__nv_bfloat162*)l)[2 * i]     = l0;
    ((__nv_bfloat162*)l)[2 * i + 1] = l1;
}

__global__ void cvt_all(const float* s0, __nv_bfloat16* h0, __nv_bfloat16* l0,
                        const float* s1, __nv_bfloat16* h1, __nv_bfloat16* l1,
                        const float* s2, __nv_bfloat16* h2, __nv_bfloat16* l2,
                        const float* s3, __nv_bfloat16* h3, __nv_bfloat16* l3,
                        const float* s4, __nv_bfloat16* h4, __nv_bfloat16* l4)
{
    int i = blockIdx.x * blockDim.x + threadIdx.x;
    if (i < CVT_N0)      cvt_one(s0, h0, l0, i);
    else if (i < CVT_N1) cvt_one(s1, h1, l1, i - CVT_N0);
    else if (i < CVT_N2) cvt_one(s2, h2, l2, i - CVT_N1);
    else if (i < CVT_N3) cvt_one(s3, h3, l3, i - CVT_N2);
    else if (i < CVT_N4) cvt_one(s4, h4, l4, i - CVT_N3);
}

// ===========================================================================
// 4-warp split-bf16 GEMM: CTA tile 128x64, warp tile 64x32, BK=32, 3 stages,
// 3 CTAs/SM.  Chunk body restructured for issue interleaving:
//   1) all A fragments for the chunk preloaded (16 independent ldsm)
//   2) cp.async prefetch issued between A-frag loads and the MMA stream
//   3) B fragments streamed per 24-MMA group (2 ldsm each)
// C = Ah*Bh + Ah*Bl + Al*Bh (fp32 acc).  EPI==1: softplus(C + bias[n]).
// ===========================================================================
#define T4_A      8192               // 128 rows x 64B
#define T4_B      4096               // 64 rows x 64B
#define T4_STAGE  (2 * T4_A + 2 * T4_B)      // 24KB
#define T4_NSTG   3
#define T4_SMEM   (T4_NSTG * T4_STAGE)       // 72KB

__device__ __forceinline__ void t4_loadA(
    const __nv_bfloat16* __restrict__ src, int ld, int row0, int k0,
    uint32_t dstbase, int tid)
{
#pragma unroll
    for (int i = 0; i < 4; i++) {
        const int u   = tid + i * 128;        // 0..511
        const int row = u >> 2;               // 0..127
        const int s   = u & 3;
        const uint32_t off = (uint32_t)(row * 64 + ((s * 16) ^ ((row & 6) << 3)));
        cpa16f(dstbase + off, src + (size_t)(row0 + row) * ld + k0 + s * 8);
    }
}
template <bool GUARD>
__device__ __forceinline__ void t4_loadB(
    const __nv_bfloat16* __restrict__ src, int ld, int row0, int k0,
    uint32_t dstbase, int tid, int nrows)
{
#pragma unroll
    for (int i = 0; i < 2; i++) {
        const int u   = tid + i * 128;        // 0..255
        const int row = u >> 2;               // 0..63
        const int s   = u & 3;
        const uint32_t off = (uint32_t)(row * 64 + ((s * 16) ^ ((row & 6) << 3)));
        if (GUARD) {
            const int ok = (row0 + row) < nrows;
            const void* p = src + (size_t)(row0 + (ok ? row : 0)) * ld + k0 + s * 8;
            cpa16(dstbase + off, p, ok ? 16 : 0);
        } else {
            cpa16f(dstbase + off, src + (size_t)(row0 + row) * ld + k0 + s * 8);
        }
    }
}

template <int EPI, bool GUARD>
__global__ void __launch_bounds__(128, 3)
tgemm4(const __nv_bfloat16* __restrict__ Ah, const __nv_bfloat16* __restrict__ Al, int lda,
       const __nv_bfloat16* __restrict__ Bh, const __nv_bfloat16* __restrict__ Bl, int ldb,
       float* __restrict__ C, int ldc, int Nc, int klen,
       const float* __restrict__ bias, size_t partStride)
{
    extern __shared__ __align__(1024) char smem[];
    const uint32_t sbase = smem_u32(smem);

    const int tid  = threadIdx.x;
    const int wid  = tid >> 5;
    const int lane = tid & 31;
    const int m0   = blockIdx.y * 128;
    const int n0   = blockIdx.x * 64;
    const int kb   = blockIdx.z * klen;
    C += (size_t)blockIdx.z * partStride;
    const int wm   = wid >> 1;             // 0..1 -> 64-row slab
    const int wn   = wid & 1;              // 0..1 -> 32-col slab

    const uint32_t khiA = (uint32_t)((lane >> 4) * 16);
    const uint32_t khiB = (uint32_t)(((lane >> 3) & 1) * 16);
    uint32_t pA[4], xA[4], pB[2], xB[2];
#pragma unroll
    for (int i = 0; i < 4; i++) {
        const int r = wm * 64 + i * 16 + (lane & 15);
        pA[i] = (uint32_t)(r * 64);
        xA[i] = (uint32_t)((r & 6) << 3);
    }
#pragma unroll
    for (int j2 = 0; j2 < 2; j2++) {
        const int r = wn * 32 + j2 * 16 + ((lane >> 4) << 3) + (lane & 7);
        pB[j2] = (uint32_t)(r * 64);
        xB[j2] = (uint32_t)((r & 6) << 3);
    }

    float acc[4][4][4];
#pragma unroll
    for (int i = 0; i < 4; i++)
#pragma unroll
        for (int j = 0; j < 4; j++)
#pragma unroll
            for (int r = 0; r < 4; r++) acc[i][j][r] = 0.f;

    const int nch = klen >> 5;

#pragma unroll
    for (int s = 0; s < T4_NSTG - 1; s++) {
        if (s < nch) {
            uint32_t st = sbase + s * T4_STAGE;
            const int k0 = kb + (s << 5);
            t4_loadA(Ah, lda, m0, k0, st,            tid);
            t4_loadA(Al, lda, m0, k0, st + T4_A,     tid);
            t4_loadB<GUARD>(Bh, ldb, n0, k0, st + 2 * T4_A,        tid, Nc);
            t4_loadB<GUARD>(Bl, ldb, n0, k0, st + 2 * T4_A + T4_B, tid, Nc);
        }
        cpa_commit();
    }

    for (int c = 0; c < nch; c++) {
        cpa_wait<T4_NSTG - 2>();
        __syncthreads();

        const uint32_t aH = sbase + (c % T4_NSTG) * T4_STAGE;
        const uint32_t aL = aH + T4_A;
        const uint32_t bH = aH + 2 * T4_A;
        const uint32_t bL = bH + T4_B;

        // (1) preload ALL A fragments for this chunk (16 independent ldsm)
        uint32_t ah[2][4][4], al[2][4][4];
#pragma unroll
        for (int ks = 0; ks < 2; ks++) {
            const uint32_t kA = (uint32_t)(ks * 32) + khiA;
#pragma unroll
            for (int i = 0; i < 4; i++) {
                ldsm_x4(ah[ks][i], aH + pA[i] + (kA ^ xA[i]));
                ldsm_x4(al[ks][i], aL + pA[i] + (kA ^ xA[i]));
            }
        }

        // (2) prefetch stage c+2 — issue overlaps A-frag scoreboard waits
        const int cp = c + T4_NSTG - 1;
        if (cp < nch) {
            uint32_t st = sbase + (cp % T4_NSTG) * T4_STAGE;
            const int k0 = kb + (cp << 5);
            t4_loadA(Ah, lda, m0, k0, st,            tid);
            t4_loadA(Al, lda, m0, k0, st + T4_A,     tid);
            t4_loadB<GUARD>(Bh, ldb, n0, k0, st + 2 * T4_A,        tid, Nc);
            t4_loadB<GUARD>(Bl, ldb, n0, k0, st + 2 * T4_A + T4_B, tid, Nc);
        }
        cpa_commit();

        // (3) B-streamed MMA groups: 2 ldsm + 24 MMA per (ks, j2)
#pragma unroll
        for (int ks = 0; ks < 2; ks++) {
            const uint32_t kB = (uint32_t)(ks * 32) + khiB;
#pragma unroll
            for (int j2 = 0; j2 < 2; j2++) {
                uint32_t bh[4], bl[4];
                ldsm_x4(bh, bH + pB[j2] + (kB ^ xB[j2]));
                ldsm_x4(bl, bL + pB[j2] + (kB ^ xB[j2]));
#pragma unroll
                for (int i = 0; i < 4; i++) {
                    mma_bf16(acc[i][2 * j2 + 0], ah[ks][i], &bh[0]);
                    mma_bf16(acc[i][2 * j2 + 1], ah[ks][i], &bh[2]);
                }
#pragma unroll
                for (int i = 0; i < 4; i++) {
                    mma_bf16(acc[i][2 * j2 + 0], ah[ks][i], &bl[0]);
                    mma_bf16(acc[i][2 * j2 + 1], ah[ks][i], &bl[2]);
                }
#pragma unroll
                for (int i = 0; i < 4; i++) {
                    mma_bf16(acc[i][2 * j2 + 0], al[ks][i], &bh[0]);
                    mma_bf16(acc[i][2 * j2 + 1], al[ks][i], &bh[2]);
                }
            }
        }
    }

    const int qr = lane >> 2;
    const int qc = (lane & 3) * 2;
#pragma unroll
    for (int i = 0; i < 4; i++) {
        const int r0 = m0 + wm * 64 + i * 16 + qr;
#pragma unroll
        for (int j = 0; j < 4; j++) {
            const int nn = n0 + wn * 32 + j * 8 + qc;
            if (!GUARD || nn < Nc) {
                float2 v0 = make_float2(acc[i][j][0], acc[i][j][1]);
                float2 v1 = make_float2(acc[i][j][2], acc[i][j][3]);
                if (EPI == 1) {
                    const float b0 = bias[nn], b1 = bias[nn + 1];
                    v0.x = softplusf(v0.x + b0); v0.y = softplusf(v0.y + b1);
                    v1.x = softplusf(v1.x + b0); v1.y = softplusf(v1.y + b1);
                }
                *(float2*)(C + (size_t)r0 * ldc + nn)       = v0;
                *(float2*)(C + (size_t)(r0 + 8) * ldc + nn) = v1;
            }
        }
    }
}

// ---------------------------------------------------------------------------
// 8-warp split-bf16 GEMM (128x128 tile, 2 CTAs/SM) — out_proj (control, unchanged)
// ---------------------------------------------------------------------------
#define TILE_BYTES  8192
#define STAGE_BYTES (4 * TILE_BYTES)
#define NSTAGE      3
#define DYN_SMEM    (NSTAGE * STAGE_BYTES)

__device__ __forceinline__ void load_tile_async8(
    const __nv_bfloat16* __restrict__ src, int ld, int row0, int k0,
    uint32_t dstbase, int tid)
{
#pragma unroll
    for (int i = 0; i < 2; i++) {
        const int u   = tid + i * 256;
        const int row = u >> 2;
        const int s   = u & 3;
        const uint32_t off = (uint32_t)(row * 64 + ((s * 16) ^ ((row & 6) << 3)));
        cpa16f(dstbase + off, src + (size_t)(row0 + row) * ld + k0 + s * 8);
    }
}

__global__ void __launch_bounds__(256, 2)
tgemm8(const __nv_bfloat16* __restrict__ Ah, const __nv_bfloat16* __restrict__ Al, int lda,
       const __nv_bfloat16* __restrict__ Bh, const __nv_bfloat16* __restrict__ Bl, int ldb,
       float* __restrict__ C, int ldc, int klen)
{
    extern __shared__ __align__(1024) char smem[];
    const uint32_t sbase = smem_u32(smem);

    const int tid  = threadIdx.x;
    const int wid  = tid >> 5;
    const int lane = tid & 31;
    const int m0   = blockIdx.y * 128;
    const int n0   = blockIdx.x * 128;
    const int wm   = wid >> 2;
    const int wn   = wid & 3;

    const uint32_t khiA = (uint32_t)((lane >> 4) * 16);
    const uint32_t khiB = (uint32_t)(((lane >> 3) & 1) * 16);
    uint32_t pA[4], xA[4], pB[2], xB[2];
#pragma unroll
    for (int i = 0; i < 4; i++) {
        const int r = wm * 64 + i * 16 + (lane & 15);
        pA[i] = (uint32_t)(r * 64);
        xA[i] = (uint32_t)((r & 6) << 3);
    }
#pragma unroll
    for (int j2 = 0; j2 < 2; j2++) {
        const int r = wn * 32 + j2 * 16 + ((lane >> 4) << 3) + (lane & 7);
        pB[j2] = (uint32_t)(r * 64);
        xB[j2] = (uint32_t)((r & 6) << 3);
    }

    float acc[4][4][4];
#pragma unroll
    for (int i = 0; i < 4; i++)
#pragma unroll
        for (int j = 0; j < 4; j++)
#pragma unroll
            for (int r = 0; r < 4; r++) acc[i][j][r] = 0.f;

    const int nch = klen >> 5;

#pragma unroll
    for (int s = 0; s < NSTAGE - 1; s++) {
        if (s < nch) {
            uint32_t st = sbase + s * STAGE_BYTES;
            const int k0 = s << 5;
            load_tile_async8(Ah, lda, m0, k0, st,                  tid);
            load_tile_async8(Al, lda, m0, k0, st + TILE_BYTES,     tid);
            load_tile_async8(Bh, ldb, n0, k0, st + 2 * TILE_BYTES, tid);
            load_tile_async8(Bl, ldb, n0, k0, st + 3 * TILE_BYTES, tid);
        }
        cpa_commit();
    }

    for (int c = 0; c < nch; c++) {
        cpa_wait<NSTAGE - 2>();
        __syncthreads();

        const int cp = c + NSTAGE - 1;
        if (cp < nch) {
            uint32_t st = sbase + (cp % NSTAGE) * STAGE_BYTES;
            const int k0 = cp << 5;
            load_tile_async8(Ah, lda, m0, k0, st,                  tid);
            load_tile_async8(Al, lda, m0, k0, st + TILE_BYTES,     tid);
            load_tile_async8(Bh, ldb, n0, k0, st + 2 * TILE_BYTES, tid);
            load_tile_async8(Bl, ldb, n0, k0, st + 3 * TILE_BYTES, tid);
        }
        cpa_commit();

        const uint32_t aH = sbase + (c % NSTAGE) * STAGE_BYTES;
        const uint32_t aL = aH + TILE_BYTES;
        const uint32_t bH = aH + 2 * TILE_BYTES;
        const uint32_t bL = aH + 3 * TILE_BYTES;

#pragma unroll
        for (int ks = 0; ks < 2; ks++) {
            const uint32_t kA = (uint32_t)(ks * 32) + khiA;
            const uint32_t kB = (uint32_t)(ks * 32) + khiB;
            uint32_t ah[4][4], al[4][4];
#pragma unroll
            for (int i = 0; i < 4; i++) {
                ldsm_x4(ah[i], aH + pA[i] + (kA ^ xA[i]));
                ldsm_x4(al[i], aL + pA[i] + (kA ^ xA[i]));
            }
            uint32_t bh[2][4], bl[2][4];
#pragma unroll
            for (int j2 = 0; j2 < 2; j2++) {
                ldsm_x4(bh[j2], bH + pB[j2] + (kB ^ xB[j2]));
                ldsm_x4(bl[j2], bL + pB[j2] + (kB ^ xB[j2]));
            }
#pragma unroll
            for (int j = 0; j < 4; j++)
#pragma unroll
                for (int i = 0; i < 4; i++)
                    mma_bf16(acc[i][j], ah[i], &bh[j >> 1][(j & 1) * 2]);
#pragma unroll
            for (int j = 0; j < 4; j++)
#pragma unroll
                for (int i = 0; i < 4; i++)
                    mma_bf16(acc[i][j], ah[i], &bl[j >> 1][(j & 1) * 2]);
#pragma unroll
            for (int j = 0; j < 4; j++)
#pragma unroll
                for (int i = 0; i < 4; i++)
                    mma_bf16(acc[i][j], al[i], &bh[j >> 1][(j & 1) * 2]);
        }
    }

    const int qr = lane >> 2;
    const int qc = (lane & 3) * 2;
#pragma unroll
    for (int i = 0; i < 4; i++) {
        const int r0 = m0 + wm * 64 + i * 16 + qr;
#pragma unroll
        for (int j = 0; j < 4; j++) {
            const int nn = n0 + wn * 32 + j * 8 + qc;
            *(float2*)(C + (size_t)r0 * ldc + nn)       = make_float2(acc[i][j][0], acc[i][j][1]);
            *(float2*)(C + (size_t)(r0 + 8) * ldc + nn) = make_float2(acc[i][j][2], acc[i][j][3]);
        }
    }
}

// ---------------------------------------------------------------------------
// split-K reduce for x_proj: sp = sum(partials); also emit bf16 hi/lo
// ---------------------------------------------------------------------------
__global__ void xp_reduce(const float* __restrict__ part,
                          float* __restrict__ sp,
                          __nv_bfloat16* __restrict__ sph,
                          __nv_bfloat16* __restrict__ spl)
{
    const int n4 = BL * SP_W / 4;
    int i = blockIdx.x * blockDim.x + threadIdx.x;
    if (i >= n4) return;
    float4 a = ((const float4*)part)[i];
#pragma unroll
    for (int p = 1; p < XP_SPLIT; p++) {
        float4 b = ((const float4*)part)[i + (size_t)p * n4];
        a.x += b.x; a.y += b.y; a.z += b.z; a.w += b.w;
    }
    ((float4*)sp)[i] = a;
    __nv_bfloat162 h0 = __floats2bfloat162_rn(a.x, a.y);
    __nv_bfloat162 h1 = __floats2bfloat162_rn(a.z, a.w);
    __nv_bfloat162 l0 = __floats2bfloat162_rn(a.x - __low2float(h0), a.y - __high2float(h0));
    __nv_bfloat162 l1 = __floats2bfloat162_rn(a.z - __low2float(h1), a.w - __high2float(h1));
    ((__nv_bfloat162*)sph)[2 * i]     = h0;
    ((__nv_bfloat162*)sph)[2 * i + 1] = h1;
    ((__nv_bfloat162*)spl)[2 * i]     = l0;
    ((__nv_bfloat162*)spl)[2 * i + 1] = l1;
}

// ---------------------------------------------------------------------------
// Depthwise causal conv1d (K=4) + bias + silu -> bf16 hi/lo
// Tiled: each thread computes 4 consecutive l for one d (7 loads / 4 outputs)
// ---------------------------------------------------------------------------
__global__ void conv_silu_kernel(const float* __restrict__ proj,
                                 const float* __restrict__ cw,
                                 const float* __restrict__ cb,
                                 __nv_bfloat16* __restrict__ uh,
                                 __nv_bfloat16* __restrict__ ul)
{
    const int t = blockIdx.x * blockDim.x + threadIdx.x;
    if (t >= (BL / 4) * DDIM) return;
    const int d   = t & (DDIM - 1);
    const int q   = t >> 12;          // 0 .. BL/4-1
    const int bl0 = q * 4;
    const int l0  = bl0 & (LSEQ - 1);

    const float4 w = *(const float4*)(cw + d * 4);
    const float  b = cb[d];
    const float* base = proj + (size_t)bl0 * P2D + d;
    const bool   lz = (l0 == 0);

    float x[7];
#pragma unroll
    for (int i = 0; i < 7; i++)
        x[i] = (!lz || i >= 3) ? base[(i - 3) * P2D] : 0.f;

#pragma unroll
    for (int k = 0; k < 4; k++) {
        float acc = b;
        acc = fmaf(w.x, x[k],     acc);
        acc = fmaf(w.y, x[k + 1], acc);
        acc = fmaf(w.z, x[k + 2], acc);
        acc = fmaf(w.w, x[k + 3], acc);
        const float v = siluf(acc);
        const __nv_bfloat16 h = __float2bfloat16(v);
        const size_t off = (size_t)(bl0 + k) * DDIM + d;
        uh[off] = h;
        ul[off] = __float2bfloat16(v - __bfloat162float(h));
    }
}

// ---------------------------------------------------------------------------
// Selective scan (state-in-register, shfl reduction, fused gate epilogue)
// ---------------------------------------------------------------------------
__global__ void __launch_bounds__(256)
scan_kernel(const float* __restrict__ dtg,
            const __nv_bfloat16* __restrict__ uhg,
            const __nv_bfloat16* __restrict__ ulg,
            const float* __restrict__ spg,
            const float* __restrict__ Alog,
            const float* __restrict__ Dp,
            const float* __restrict__ proj,
            __nv_bfloat16* __restrict__ yh,
            __nv_bfloat16* __restrict__ yl)
{
    const int b   = blockIdx.y;
    const int d0  = blockIdx.x * 16;
    const int t   = threadIdx.x;
    const int seq = t >> 4;
    const int n   = t & 15;
    const int d   = d0 + seq;

    __shared__ float sdt[64][16];
    __shared__ float su [64][16];
    __shared__ float sB [64][16];
    __shared__ float sC [64][16];
    __shared__ float sy [64][16];

    const float a = -__expf(Alog[d * NSTATE + n]);
    float s = 0.f;

    const int i16 = t >> 4, j16 = t & 15;
    const int i32 = t >> 5, j32 = t & 31;

    for (int l0 = 0; l0 < LSEQ; l0 += 64) {
        const int bl0 = b * LSEQ + l0;
#pragma unroll
        for (int r = 0; r < 4; r++) {
            const int ii = i16 + r * 16;
            const size_t off = (size_t)(bl0 + ii) * DDIM + d0 + j16;
            sdt[ii][j16] = dtg[off];
            su [ii][j16] = __bfloat162float(uhg[off]) + __bfloat162float(ulg[off]);
        }
#pragma unroll
        for (int r = 0; r < 8; r++) {
            const int ii = i32 + r * 8;
            const float v = spg[(size_t)(bl0 + ii) * SP_W + RRANK + j32];
            if (j32 < 16) sB[ii][j32] = v;
            else          sC[ii][j32 - 16] = v;
        }
        __syncthreads();

#pragma unroll 4
        for (int il = 0; il < 64; il++) {
            const float dtv = sdt[il][seq];
            const float dA  = __expf(a * dtv);
            const float dBu = dtv * sB[il][n] * su[il][seq];
            s = fmaf(dA, s, dBu);
            float p = s * sC[il][n];
            p += __shfl_xor_sync(0xffffffffu, p, 8);
            p += __shfl_xor_sync(0xffffffffu, p, 4);
            p += __shfl_xor_sync(0xffffffffu, p, 2);
            p += __shfl_xor_sync(0xffffffffu, p, 1);
            if (n == 0) sy[il][seq] = p;
        }
        __syncthreads();

#pragma unroll
        for (int r = 0; r < 4; r++) {
            const int ii = i16 + r * 16;
            const float yy = sy[ii][j16];
            const float uu = su[ii][j16];
            const float g  = proj[(size_t)(bl0 + ii) * P2D + DDIM + d0 + j16];
            const float yf = fmaf(uu, Dp[d0 + j16], yy) * siluf(g);
            const size_t off = (size_t)(bl0 + ii) * DDIM + d0 + j16;
            const __nv_bfloat16 h = __float2bfloat16(yf);
            yh[off] = h;
            yl[off] = __float2bfloat16(yf - __bfloat162float(h));
        }
        __syncthreads();
    }
}

// ---------------------------------------------------------------------------
// Launch sequence (graph-capturable: kernel launches only)
// ---------------------------------------------------------------------------
extern "C" void kernel_launch(void* const* d_in, const int* in_sizes, int n_in,
                              void* d_out, int out_size)
{
    const float* hs   = (const float*)d_in[0];
    const float* w_in = (const float*)d_in[1];
    const float* cw   = (const float*)d_in[2];
    const float* cb   = (const float*)d_in[3];
    const float* w_x  = (const float*)d_in[4];
    const float* w_dt = (const float*)d_in[5];
    const float* b_dt = (const float*)d_in[6];
    const float* alog = (const float*)d_in[7];
    const float* dpar = (const float*)d_in[8];
    const float* w_o  = (const float*)d_in[9];
    float* out = (float*)d_out;

    float *proj, *sp, *dtb, *xpp;
    __nv_bfloat16 *hs_h, *hs_l, *win_h, *win_l, *u_h, *u_l, *wx_h, *wx_l;
    __nv_bfloat16 *sp_h, *sp_l, *wdt_h, *wdt_l, *y_h, *y_l, *wo_h, *wo_l;
    cudaGetSymbolAddress((void**)&proj,  g_proj);
    cudaGetSymbolAddress((void**)&sp,    g_sp);
    cudaGetSymbolAddress((void**)&dtb,   g_dt);
    cudaGetSymbolAddress((void**)&xpp,   g_xpp);
    cudaGetSymbolAddress((void**)&hs_h,  g_hs_h);  cudaGetSymbolAddress((void**)&hs_l,  g_hs_l);
    cudaGetSymbolAddress((void**)&win_h, g_win_h); cudaGetSymbolAddress((void**)&win_l, g_win_l);
    cudaGetSymbolAddress((void**)&u_h,   g_u_h);   cudaGetSymbolAddress((void**)&u_l,   g_u_l);
    cudaGetSymbolAddress((void**)&wx_h,  g_wx_h);  cudaGetSymbolAddress((void**)&wx_l,  g_wx_l);
    cudaGetSymbolAddress((void**)&sp_h,  g_sp_h);  cudaGetSymbolAddress((void**)&sp_l,  g_sp_l);
    cudaGetSymbolAddress((void**)&wdt_h, g_wdt_h); cudaGetSymbolAddress((void**)&wdt_l, g_wdt_l);
    cudaGetSymbolAddress((void**)&y_h,   g_y_h);   cudaGetSymbolAddress((void**)&y_l,   g_y_l);
    cudaGetSymbolAddress((void**)&wo_h,  g_wo_h);  cudaGetSymbolAddress((void**)&wo_l,  g_wo_l);

    cudaFuncSetAttribute(tgemm4<0, false>, cudaFuncAttributeMaxDynamicSharedMemorySize, T4_SMEM);
    cudaFuncSetAttribute(tgemm4<0, true>,  cudaFuncAttributeMaxDynamicSharedMemorySize, T4_SMEM);
    cudaFuncSetAttribute(tgemm4<1, false>, cudaFuncAttributeMaxDynamicSharedMemorySize, T4_SMEM);
    cudaFuncSetAttribute(tgemm8,           cudaFuncAttributeMaxDynamicSharedMemorySize, DYN_SMEM);

    // 0) all fp32 -> bf16 hi/lo conversions in ONE launch
    cvt_all<<<(CVT_N4 + 255) / 256, 256>>>(
        hs, hs_h, hs_l, w_in, win_h, win_l, w_x, wx_h, wx_l,
        w_dt, wdt_h, wdt_l, w_o, wo_h, wo_l);

    // 1) in_proj: proj[2048, 8192] = hs @ w_in^T   (128x64 tiles, 3 CTA/SM)
    tgemm4<0, false><<<dim3(P2D / 64, BL / 128, 1), 128, T4_SMEM>>>(
        hs_h, hs_l, HDIM, win_h, win_l, HDIM, proj, P2D, P2D, HDIM, nullptr, 0);

    // 2) conv + silu -> u (hi/lo)  (tiled: 4 l per thread)
    conv_silu_kernel<<<(BL / 4 * DDIM) / 256, 256>>>(proj, cw, cb, u_h, u_l);

    // 3) x_proj split-K: partials[8][2048, 160] = u @ w_x^T
    tgemm4<0, true><<<dim3(3, BL / 128, XP_SPLIT), 128, T4_SMEM>>>(
        u_h, u_l, DDIM, wx_h, wx_l, DDIM, xpp, SP_W, SP_W, XP_KLEN,
        nullptr, (size_t)BL * SP_W);

    // 3b) reduce partials -> sp (fp32) + sp hi/lo (bf16)
    xp_reduce<<<(BL * SP_W / 4 + 255) / 256, 256>>>(xpp, sp, sp_h, sp_l);

    // 4) dt_proj + bias + softplus: dt[2048, 4096]
    tgemm4<1, false><<<dim3(DDIM / 64, BL / 128, 1), 128, T4_SMEM>>>(
        sp_h, sp_l, SP_W, wdt_h, wdt_l, RRANK, dtb, DDIM, DDIM, RRANK, b_dt, 0);

    // 5) selective scan + D-skip + gate (fused) -> y (hi/lo)
    scan_kernel<<<dim3(DDIM / 16, BSZ), 256>>>(dtb, u_h, u_l, sp, alog, dpar, proj, y_h, y_l);

    // 6) out_proj: out[2048, 2048] = y @ w_o^T   (128x128 tiles, 2 CTA/SM)
    tgemm8<<<dim3(HDIM / 128, BL / 128, 1), 256, DYN_SMEM>>>(
        y_h, y_l, DDIM, wo_h, wo_l, DDIM, out, HDIM, DDIM);
}

// round 9
// speedup vs baseline: 1.3375x; 1.3375x over previous
#include <cuda_runtime.h>
#include <cuda_bf16.h>
#include <cuda_fp16.h>
#include <math.h>
#include <stdint.h>

// Problem constants (fixed by setup_inputs)
#define BSZ    2
#define LSEQ   1024
#define HDIM   2048
#define DDIM   4096
#define NSTATE 16
#define RRANK  128
#define KCONV  4
#define BL     (BSZ * LSEQ)          // 2048 rows
#define P2D    (2 * DDIM)            // 8192
#define SP_W   (RRANK + 2 * NSTATE)  // 160
#define XP_SPLIT 8
#define XP_KLEN  (DDIM / XP_SPLIT)   // 512

// ---------------------------------------------------------------------------
// Scratch: static device globals (no cudaMalloc allowed)
// ---------------------------------------------------------------------------
__device__ float g_proj[(size_t)BL * P2D];
__device__ float g_sp  [(size_t)BL * SP_W];
__device__ float g_dt  [(size_t)BL * DDIM];
__device__ float g_xpp [(size_t)XP_SPLIT * BL * SP_W];

// fp16 operands for in_proj / out_proj (2-term scheme)
__device__ __half g_hs_f [(size_t)BL * HDIM];
__device__ __half g_win_fh[(size_t)P2D * HDIM],  g_win_fl[(size_t)P2D * HDIM];
__device__ __half g_y_f  [(size_t)BL * DDIM];
__device__ __half g_wo_fh[(size_t)HDIM * DDIM], g_wo_fl[(size_t)HDIM * DDIM];

// bf16 hi/lo operands for x_proj / dt_proj (3-term scheme)
__device__ __nv_bfloat16 g_u_h[(size_t)BL * DDIM],   g_u_l[(size_t)BL * DDIM];
__device__ __nv_bfloat16 g_wx_h[(size_t)SP_W * DDIM], g_wx_l[(size_t)SP_W * DDIM];
__device__ __nv_bfloat16 g_sp_h[(size_t)BL * SP_W],  g_sp_l[(size_t)BL * SP_W];
__device__ __nv_bfloat16 g_wdt_h[(size_t)DDIM * RRANK], g_wdt_l[(size_t)DDIM * RRANK];

__device__ __forceinline__ float softplusf(float x) {
    return (x > 20.f) ? x : log1pf(__expf(x));
}
__device__ __forceinline__ float siluf(float x) {
    return x / (1.f + __expf(-x));
}

// ---------------------------------------------------------------------------
// PTX helpers
// ---------------------------------------------------------------------------
__device__ __forceinline__ uint32_t smem_u32(const void* p) {
    uint32_t a;
    asm("{ .reg .u64 t; cvta.to.shared.u64 t, %1; cvt.u32.u64 %0, t; }" : "=r"(a) : "l"(p));
    return a;
}
__device__ __forceinline__ void cpa16(uint32_t dst, const void* src, int sz) {
    asm volatile("cp.async.cg.shared.global [%0], [%1], 16, %2;"
                 :: "r"(dst), "l"(src), "r"(sz) : "memory");
}
__device__ __forceinline__ void cpa16f(uint32_t dst, const void* src) {
    asm volatile("cp.async.cg.shared.global [%0], [%1], 16;"
                 :: "r"(dst), "l"(src) : "memory");
}
__device__ __forceinline__ void cpa_commit() {
    asm volatile("cp.async.commit_group;" ::: "memory");
}
template <int N>
__device__ __forceinline__ void cpa_wait() {
    asm volatile("cp.async.wait_group %0;" :: "n"(N) : "memory");
}
__device__ __forceinline__ void ldsm_x4(uint32_t* r, uint32_t addr) {
    asm volatile("ldmatrix.sync.aligned.m8n8.x4.shared.b16 {%0,%1,%2,%3}, [%4];"
                 : "=r"(r[0]), "=r"(r[1]), "=r"(r[2]), "=r"(r[3]) : "r"(addr));
}
__device__ __forceinline__ void mma_bf16(float* c, const uint32_t* a, const uint32_t* b) {
    asm volatile(
        "mma.sync.aligned.m16n8k16.row.col.f32.bf16.bf16.f32 "
        "{%0,%1,%2,%3}, {%4,%5,%6,%7}, {%8,%9}, {%0,%1,%2,%3};"
        : "+f"(c[0]), "+f"(c[1]), "+f"(c[2]), "+f"(c[3])
        : "r"(a[0]), "r"(a[1]), "r"(a[2]), "r"(a[3]), "r"(b[0]), "r"(b[1]));
}
__device__ __forceinline__ void mma_f16(float* c, const uint32_t* a, const uint32_t* b) {
    asm volatile(
        "mma.sync.aligned.m16n8k16.row.col.f32.f16.f16.f32 "
        "{%0,%1,%2,%3}, {%4,%5,%6,%7}, {%8,%9}, {%0,%1,%2,%3};"
        : "+f"(c[0]), "+f"(c[1]), "+f"(c[2]), "+f"(c[3])
        : "r"(a[0]), "r"(a[1]), "r"(a[2]), "r"(a[3]), "r"(b[0]), "r"(b[1]));
}

// ---------------------------------------------------------------------------
// Merged conversions (1 launch):
//   hs -> fp16 single, w_in -> fp16 hi/lo, w_x -> bf16 hi/lo,
//   w_dt -> bf16 hi/lo, w_o -> fp16 hi/lo
// ---------------------------------------------------------------------------
#define CVT_N0 (BL * HDIM / 4)
#define CVT_N1 (CVT_N0 + P2D * HDIM / 4)
#define CVT_N2 (CVT_N1 + SP_W * DDIM / 4)
#define CVT_N3 (CVT_N2 + DDIM * RRANK / 4)
#define CVT_N4 (CVT_N3 + HDIM * DDIM / 4)

__device__ __forceinline__ void cvt_bf16_hl(const float* __restrict__ x,
                                            __nv_bfloat16* __restrict__ h,
                                            __nv_bfloat16* __restrict__ l, int i)
{
    float4 v = ((const float4*)x)[i];
    __nv_bfloat162 h0 = __floats2bfloat162_rn(v.x, v.y);
    __nv_bfloat162 h1 = __floats2bfloat162_rn(v.z, v.w);
    __nv_bfloat162 l0 = __floats2bfloat162_rn(v.x - __low2float(h0), v.y - __high2float(h0));
    __nv_bfloat162 l1 = __floats2bfloat162_rn(v.z - __low2float(h1), v.w - __high2float(h1));
    ((__nv_bfloat162*)h)[2 * i]     = h0;
    ((__nv_bfloat162*)h)[2 * i + 1] = h1;
    ((__nv_bfloat162*)l)[2 * i]     = l0;
    ((__nv_bfloat162*)l)[2 * i + 1] = l1;
}
__device__ __forceinline__ void cvt_f16_hl(const float* __restrict__ x,
                                           __half* __restrict__ h,
                                           __half* __restrict__ l, int i)
{
    float4 v = ((const float4*)x)[i];
    __half2 h0 = __floats2half2_rn(v.x, v.y);
    __half2 h1 = __floats2half2_rn(v.z, v.w);
    __half2 l0 = __floats2half2_rn(v.x - __low2float(h0), v.y - __high2float(h0));
    __half2 l1 = __floats2half2_rn(v.z - __low2float(h1), v.w - __high2float(h1));
    ((__half2*)h)[2 * i]     = h0;
    ((__half2*)h)[2 * i + 1] = h1;
    ((__half2*)l)[2 * i]     = l0;
    ((__half2*)l)[2 * i + 1] = l1;
}
__device__ __forceinline__ void cvt_f16_s(const float* __restrict__ x,
                                          __half* __restrict__ h, int i)
{
    float4 v = ((const float4*)x)[i];
    ((__half2*)h)[2 * i]     = __floats2half2_rn(v.x, v.y);
    ((__half2*)h)[2 * i + 1] = __floats2half2_rn(v.z, v.w);
}

__global__ void cvt_all(const float* hs,  __half* hsf,
                        const float* win, __half* winh, __half* winl,
                        const float* wx,  __nv_bfloat16* wxh, __nv_bfloat16* wxl,
                        const float* wdt, __nv_bfloat16* wdh, __nv_bfloat16* wdl,
                        const float* wo,  __half* woh, __half* wol)
{
    int i = blockIdx.x * blockDim.x + threadIdx.x;
    if (i < CVT_N0)      cvt_f16_s (hs,  hsf,        i);
    else if (i < CVT_N1) cvt_f16_hl(win, winh, winl, i - CVT_N0);
    else if (i < CVT_N2) cvt_bf16_hl(wx, wxh, wxl,   i - CVT_N1);
    else if (i < CVT_N3) cvt_bf16_hl(wdt, wdh, wdl,  i - CVT_N2);
    else if (i < CVT_N4) cvt_f16_hl(wo,  woh, wol,   i - CVT_N3);
}

// ===========================================================================
// Shared tile loaders (2-byte element types; 64B rows, SW64-style swizzle)
// ===========================================================================
template <typename T>
__device__ __forceinline__ void load128(const T* __restrict__ src, int ld,
                                        int row0, int k0, uint32_t dstbase, int tid)
{
#pragma unroll
    for (int i = 0; i < 4; i++) {
        const int u   = tid + i * 128;        // 0..511
        const int row = u >> 2;               // 0..127
        const int s   = u & 3;
        const uint32_t off = (uint32_t)(row * 64 + ((s * 16) ^ ((row & 6) << 3)));
        cpa16f(dstbase + off, src + (size_t)(row0 + row) * ld + k0 + s * 8);
    }
}
template <typename T, bool GUARD>
__device__ __forceinline__ void load64(const T* __restrict__ src, int ld,
                                       int row0, int k0, uint32_t dstbase,
                                       int tid, int nrows)
{
#pragma unroll
    for (int i = 0; i < 2; i++) {
        const int u   = tid + i * 128;        // 0..255
        const int row = u >> 2;               // 0..63
        const int s   = u & 3;
        const uint32_t off = (uint32_t)(row * 64 + ((s * 16) ^ ((row & 6) << 3)));
        if (GUARD) {
            const int ok = (row0 + row) < nrows;
            const void* p = src + (size_t)(row0 + (ok ? row : 0)) * ld + k0 + s * 8;
            cpa16(dstbase + off, p, ok ? 16 : 0);
        } else {
            cpa16f(dstbase + off, src + (size_t)(row0 + row) * ld + k0 + s * 8);
        }
    }
}

// ===========================================================================
// fp16 2-term GEMM (in_proj / out_proj):  C = A * (Bh + Bl)^T, fp32 acc.
// A single fp16 [M,K], B split fp16 hi/lo [N,K].  CTA tile 128x64, 4 warps,
// BK=32, 3 stages x 16KB = 48KB -> 4 CTAs/SM.
// ===========================================================================
#define T2_A      8192               // 128 rows x 64B
#define T2_B      4096               // 64 rows x 64B
#define T2_STAGE  (T2_A + 2 * T2_B)  // 16KB
#define T2_NSTG   3
#define T2_SMEM   (T2_NSTG * T2_STAGE)   // 48KB

__global__ void __launch_bounds__(128, 4)
tgemm2h(const __half* __restrict__ A, int lda,
        const __half* __restrict__ Bh, const __half* __restrict__ Bl, int ldb,
        float* __restrict__ C, int ldc, int klen)
{
    extern __shared__ __align__(1024) char smem[];
    const uint32_t sbase = smem_u32(smem);

    const int tid  = threadIdx.x;
    const int wid  = tid >> 5;
    const int lane = tid & 31;
    const int m0   = blockIdx.y * 128;
    const int n0   = blockIdx.x * 64;
    const int wm   = wid >> 1;
    const int wn   = wid & 1;

    const uint32_t khiA = (uint32_t)((lane >> 4) * 16);
    const uint32_t khiB = (uint32_t)(((lane >> 3) & 1) * 16);
    uint32_t pA[4], xA[4], pB[2], xB[2];
#pragma unroll
    for (int i = 0; i < 4; i++) {
        const int r = wm * 64 + i * 16 + (lane & 15);
        pA[i] = (uint32_t)(r * 64);
        xA[i] = (uint32_t)((r & 6) << 3);
    }
#pragma unroll
    for (int j2 = 0; j2 < 2; j2++) {
        const int r = wn * 32 + j2 * 16 + ((lane >> 4) << 3) + (lane & 7);
        pB[j2] = (uint32_t)(r * 64);
        xB[j2] = (uint32_t)((r & 6) << 3);
    }

    float acc[4][4][4];
#pragma unroll
    for (int i = 0; i < 4; i++)
#pragma unroll
        for (int j = 0; j < 4; j++)
#pragma unroll
            for (int r = 0; r < 4; r++) acc[i][j][r] = 0.f;

    const int nch = klen >> 5;

#pragma unroll
    for (int s = 0; s < T2_NSTG - 1; s++) {
        if (s < nch) {
            uint32_t st = sbase + s * T2_STAGE;
            const int k0 = s << 5;
            load128(A,  lda, m0, k0, st, tid);
            load64<__half, false>(Bh, ldb, n0, k0, st + T2_A,        tid, 0);
            load64<__half, false>(Bl, ldb, n0, k0, st + T2_A + T2_B, tid, 0);
        }
        cpa_commit();
    }

    for (int c = 0; c < nch; c++) {
        cpa_wait<T2_NSTG - 2>();
        __syncthreads();

        const int cp = c + T2_NSTG - 1;
        if (cp < nch) {
            uint32_t st = sbase + (cp % T2_NSTG) * T2_STAGE;
            const int k0 = cp << 5;
            load128(A,  lda, m0, k0, st, tid);
            load64<__half, false>(Bh, ldb, n0, k0, st + T2_A,        tid, 0);
            load64<__half, false>(Bl, ldb, n0, k0, st + T2_A + T2_B, tid, 0);
        }
        cpa_commit();

        const uint32_t aS = sbase + (c % T2_NSTG) * T2_STAGE;
        const uint32_t bH = aS + T2_A;
        const uint32_t bL = bH + T2_B;

#pragma unroll
        for (int ks = 0; ks < 2; ks++) {
            const uint32_t kA = (uint32_t)(ks * 32) + khiA;
            const uint32_t kB = (uint32_t)(ks * 32) + khiB;
            uint32_t ah[4][4];
#pragma unroll
            for (int i = 0; i < 4; i++)
                ldsm_x4(ah[i], aS + pA[i] + (kA ^ xA[i]));
            uint32_t bh[2][4], bl[2][4];
#pragma unroll
            for (int j2 = 0; j2 < 2; j2++) {
                ldsm_x4(bh[j2], bH + pB[j2] + (kB ^ xB[j2]));
                ldsm_x4(bl[j2], bL + pB[j2] + (kB ^ xB[j2]));
            }
#pragma unroll
            for (int j = 0; j < 4; j++)
#pragma unroll
                for (int i = 0; i < 4; i++)
                    mma_f16(acc[i][j], ah[i], &bh[j >> 1][(j & 1) * 2]);
#pragma unroll
            for (int j = 0; j < 4; j++)
#pragma unroll
                for (int i = 0; i < 4; i++)
                    mma_f16(acc[i][j], ah[i], &bl[j >> 1][(j & 1) * 2]);
        }
    }

    const int qr = lane >> 2;
    const int qc = (lane & 3) * 2;
#pragma unroll
    for (int i = 0; i < 4; i++) {
        const int r0 = m0 + wm * 64 + i * 16 + qr;
#pragma unroll
        for (int j = 0; j < 4; j++) {
            const int nn = n0 + wn * 32 + j * 8 + qc;
            *(float2*)(C + (size_t)r0 * ldc + nn)       = make_float2(acc[i][j][0], acc[i][j][1]);
            *(float2*)(C + (size_t)(r0 + 8) * ldc + nn) = make_float2(acc[i][j][2], acc[i][j][3]);
        }
    }
}

// ===========================================================================
// bf16 3-term GEMM (x_proj / dt_proj): R7-winning structure, 3 CTAs/SM.
// C = Ah*Bh + Ah*Bl + Al*Bh.  EPI==1: softplus(C + bias[n]).
// ===========================================================================
#define T4_A      8192
#define T4_B      4096
#define T4_STAGE  (2 * T4_A + 2 * T4_B)      // 24KB
#define T4_NSTG   3
#define T4_SMEM   (T4_NSTG * T4_STAGE)       // 72KB

template <int EPI, bool GUARD>
__global__ void __launch_bounds__(128, 3)
tgemm4(const __nv_bfloat16* __restrict__ Ah, const __nv_bfloat16* __restrict__ Al, int lda,
       const __nv_bfloat16* __restrict__ Bh, const __nv_bfloat16* __restrict__ Bl, int ldb,
       float* __restrict__ C, int ldc, int Nc, int klen,
       const float* __restrict__ bias, size_t partStride)
{
    extern __shared__ __align__(1024) char smem[];
    const uint32_t sbase = smem_u32(smem);

    const int tid  = threadIdx.x;
    const int wid  = tid >> 5;
    const int lane = tid & 31;
    const int m0   = blockIdx.y * 128;
    const int n0   = blockIdx.x * 64;
    const int kb   = blockIdx.z * klen;
    C += (size_t)blockIdx.z * partStride;
    const int wm   = wid >> 1;
    const int wn   = wid & 1;

    const uint32_t khiA = (uint32_t)((lane >> 4) * 16);
    const uint32_t khiB = (uint32_t)(((lane >> 3) & 1) * 16);
    uint32_t pA[4], xA[4], pB[2], xB[2];
#pragma unroll
    for (int i = 0; i < 4; i++) {
        const int r = wm * 64 + i * 16 + (lane & 15);
        pA[i] = (uint32_t)(r * 64);
        xA[i] = (uint32_t)((r & 6) << 3);
    }
#pragma unroll
    for (int j2 = 0; j2 < 2; j2++) {
        const int r = wn * 32 + j2 * 16 + ((lane >> 4) << 3) + (lane & 7);
        pB[j2] = (uint32_t)(r * 64);
        xB[j2] = (uint32_t)((r & 6) << 3);
    }

    float acc[4][4][4];
#pragma unroll
    for (int i = 0; i < 4; i++)
#pragma unroll
        for (int j = 0; j < 4; j++)
#pragma unroll
            for (int r = 0; r < 4; r++) acc[i][j][r] = 0.f;

    const int nch = klen >> 5;

#pragma unroll
    for (int s = 0; s < T4_NSTG - 1; s++) {
        if (s < nch) {
            uint32_t st = sbase + s * T4_STAGE;
            const int k0 = kb + (s << 5);
            load128(Ah, lda, m0, k0, st,        tid);
            load128(Al, lda, m0, k0, st + T4_A, tid);
            load64<__nv_bfloat16, GUARD>(Bh, ldb, n0, k0, st + 2 * T4_A,        tid, Nc);
            load64<__nv_bfloat16, GUARD>(Bl, ldb, n0, k0, st + 2 * T4_A + T4_B, tid, Nc);
        }
        cpa_commit();
    }

    for (int c = 0; c < nch; c++) {
        cpa_wait<T4_NSTG - 2>();
        __syncthreads();

        const int cp = c + T4_NSTG - 1;
        if (cp < nch) {
            uint32_t st = sbase + (cp % T4_NSTG) * T4_STAGE;
            const int k0 = kb + (cp << 5);
            load128(Ah, lda, m0, k0, st,        tid);
            load128(Al, lda, m0, k0, st + T4_A, tid);
            load64<__nv_bfloat16, GUARD>(Bh, ldb, n0, k0, st + 2 * T4_A,        tid, Nc);
            load64<__nv_bfloat16, GUARD>(Bl, ldb, n0, k0, st + 2 * T4_A + T4_B, tid, Nc);
        }
        cpa_commit();

        const uint32_t aH = sbase + (c % T4_NSTG) * T4_STAGE;
        const uint32_t aL = aH + T4_A;
        const uint32_t bH = aH + 2 * T4_A;
        const uint32_t bL = bH + T4_B;

#pragma unroll
        for (int ks = 0; ks < 2; ks++) {
            const uint32_t kA = (uint32_t)(ks * 32) + khiA;
            const uint32_t kB = (uint32_t)(ks * 32) + khiB;
            uint32_t ah[4][4], al[4][4];
#pragma unroll
            for (int i = 0; i < 4; i++) {
                ldsm_x4(ah[i], aH + pA[i] + (kA ^ xA[i]));
                ldsm_x4(al[i], aL + pA[i] + (kA ^ xA[i]));
            }
            uint32_t bh[2][4], bl[2][4];
#pragma unroll
            for (int j2 = 0; j2 < 2; j2++) {
                ldsm_x4(bh[j2], bH + pB[j2] + (kB ^ xB[j2]));
                ldsm_x4(bl[j2], bL + pB[j2] + (kB ^ xB[j2]));
            }
#pragma unroll
            for (int j = 0; j < 4; j++)
#pragma unroll
                for (int i = 0; i < 4; i++)
                    mma_bf16(acc[i][j], ah[i], &bh[j >> 1][(j & 1) * 2]);
#pragma unroll
            for (int j = 0; j < 4; j++)
#pragma unroll
                for (int i = 0; i < 4; i++)
                    mma_bf16(acc[i][j], ah[i], &bl[j >> 1][(j & 1) * 2]);
#pragma unroll
            for (int j = 0; j < 4; j++)
#pragma unroll
                for (int i = 0; i < 4; i++)
                    mma_bf16(acc[i][j], al[i], &bh[j >> 1][(j & 1) * 2]);
        }
    }

    const int qr = lane >> 2;
    const int qc = (lane & 3) * 2;
#pragma unroll
    for (int i = 0; i < 4; i++) {
        const int r0 = m0 + wm * 64 + i * 16 + qr;
#pragma unroll
        for (int j = 0; j < 4; j++) {
            const int nn = n0 + wn * 32 + j * 8 + qc;
            if (!GUARD || nn < Nc) {
                float2 v0 = make_float2(acc[i][j][0], acc[i][j][1]);
                float2 v1 = make_float2(acc[i][j][2], acc[i][j][3]);
                if (EPI == 1) {
                    const float b0 = bias[nn], b1 = bias[nn + 1];
                    v0.x = softplusf(v0.x + b0); v0.y = softplusf(v0.y + b1);
                    v1.x = softplusf(v1.x + b0); v1.y = softplusf(v1.y + b1);
                }
                *(float2*)(C + (size_t)r0 * ldc + nn)       = v0;
                *(float2*)(C + (size_t)(r0 + 8) * ldc + nn) = v1;
            }
        }
    }
}

// ---------------------------------------------------------------------------
// split-K reduce for x_proj: sp = sum(partials); also emit bf16 hi/lo
// ---------------------------------------------------------------------------
__global__ void xp_reduce(const float* __restrict__ part,
                          float* __restrict__ sp,
                          __nv_bfloat16* __restrict__ sph,
                          __nv_bfloat16* __restrict__ spl)
{
    const int n4 = BL * SP_W / 4;
    int i = blockIdx.x * blockDim.x + threadIdx.x;
    if (i >= n4) return;
    float4 a = ((const float4*)part)[i];
#pragma unroll
    for (int p = 1; p < XP_SPLIT; p++) {
        float4 b = ((const float4*)part)[i + (size_t)p * n4];
        a.x += b.x; a.y += b.y; a.z += b.z; a.w += b.w;
    }
    ((float4*)sp)[i] = a;
    __nv_bfloat162 h0 = __floats2bfloat162_rn(a.x, a.y);
    __nv_bfloat162 h1 = __floats2bfloat162_rn(a.z, a.w);
    __nv_bfloat162 l0 = __floats2bfloat162_rn(a.x - __low2float(h0), a.y - __high2float(h0));
    __nv_bfloat162 l1 = __floats2bfloat162_rn(a.z - __low2float(h1), a.w - __high2float(h1));
    ((__nv_bfloat162*)sph)[2 * i]     = h0;
    ((__nv_bfloat162*)sph)[2 * i + 1] = h1;
    ((__nv_bfloat162*)spl)[2 * i]     = l0;
    ((__nv_bfloat162*)spl)[2 * i + 1] = l1;
}

// ---------------------------------------------------------------------------
// Depthwise causal conv1d (K=4) + bias + silu -> u bf16 hi/lo
// ---------------------------------------------------------------------------
__global__ void conv_silu_kernel(const float* __restrict__ proj,
                                 const float* __restrict__ cw,
                                 const float* __restrict__ cb,
                                 __nv_bfloat16* __restrict__ uh,
                                 __nv_bfloat16* __restrict__ ul)
{
    const int t = blockIdx.x * blockDim.x + threadIdx.x;
    if (t >= (BL / 4) * DDIM) return;
    const int d   = t & (DDIM - 1);
    const int q   = t >> 12;
    const int bl0 = q * 4;
    const int l0  = bl0 & (LSEQ - 1);

    const float4 w = *(const float4*)(cw + d * 4);
    const float  b = cb[d];
    const float* base = proj + (size_t)bl0 * P2D + d;
    const bool   lz = (l0 == 0);

    float x[7];
#pragma unroll
    for (int i = 0; i < 7; i++)
        x[i] = (!lz || i >= 3) ? base[(i - 3) * P2D] : 0.f;

#pragma unroll
    for (int k = 0; k < 4; k++) {
        float acc = b;
        acc = fmaf(w.x, x[k],     acc);
        acc = fmaf(w.y, x[k + 1], acc);
        acc = fmaf(w.z, x[k + 2], acc);
        acc = fmaf(w.w, x[k + 3], acc);
        const float v = siluf(acc);
        const __nv_bfloat16 h = __float2bfloat16(v);
        const size_t off = (size_t)(bl0 + k) * DDIM + d;
        uh[off] = h;
        ul[off] = __float2bfloat16(v - __bfloat162float(h));
    }
}

// ---------------------------------------------------------------------------
// Selective scan -> y single fp16 (for fp16 2-term out_proj)
// ---------------------------------------------------------------------------
__global__ void __launch_bounds__(256)
scan_kernel(const float* __restrict__ dtg,
            const __nv_bfloat16* __restrict__ uhg,
            const __nv_bfloat16* __restrict__ ulg,
            const float* __restrict__ spg,
            const float* __restrict__ Alog,
            const float* __restrict__ Dp,
            const float* __restrict__ proj,
            __half* __restrict__ yf)
{
    const int b   = blockIdx.y;
    const int d0  = blockIdx.x * 16;
    const int t   = threadIdx.x;
    const int seq = t >> 4;
    const int n   = t & 15;
    const int d   = d0 + seq;

    __shared__ float sdt[64][16];
    __shared__ float su [64][16];
    __shared__ float sB [64][16];
    __shared__ float sC [64][16];
    __shared__ float sy [64][16];

    const float a = -__expf(Alog[d * NSTATE + n]);
    float s = 0.f;

    const int i16 = t >> 4, j16 = t & 15;
    const int i32 = t >> 5, j32 = t & 31;

    for (int l0 = 0; l0 < LSEQ; l0 += 64) {
        const int bl0 = b * LSEQ + l0;
#pragma unroll
        for (int r = 0; r < 4; r++) {
            const int ii = i16 + r * 16;
            const size_t off = (size_t)(bl0 + ii) * DDIM + d0 + j16;
            sdt[ii][j16] = dtg[off];
            su [ii][j16] = __bfloat162float(uhg[off]) + __bfloat162float(ulg[off]);
        }
#pragma unroll
        for (int r = 0; r < 8; r++) {
            const int ii = i32 + r * 8;
            const float v = spg[(size_t)(bl0 + ii) * SP_W + RRANK + j32];
            if (j32 < 16) sB[ii][j32] = v;
            else          sC[ii][j32 - 16] = v;
        }
        __syncthreads();

#pragma unroll 4
        for (int il = 0; il < 64; il++) {
            const float dtv = sdt[il][seq];
            const float dA  = __expf(a * dtv);
            const float dBu = dtv * sB[il][n] * su[il][seq];
            s = fmaf(dA, s, dBu);
            float p = s * sC[il][n];
            p += __shfl_xor_sync(0xffffffffu, p, 8);
            p += __shfl_xor_sync(0xffffffffu, p, 4);
            p += __shfl_xor_sync(0xffffffffu, p, 2);
            p += __shfl_xor_sync(0xffffffffu, p, 1);
            if (n == 0) sy[il][seq] = p;
        }
        __syncthreads();

#pragma unroll
        for (int r = 0; r < 4; r++) {
            const int ii = i16 + r * 16;
            const float yy = sy[ii][j16];
            const float uu = su[ii][j16];
            const float g  = proj[(size_t)(bl0 + ii) * P2D + DDIM + d0 + j16];
            const float yv = fmaf(uu, Dp[d0 + j16], yy) * siluf(g);
            yf[(size_t)(bl0 + ii) * DDIM + d0 + j16] = __float2half_rn(yv);
        }
        __syncthreads();
    }
}

// ---------------------------------------------------------------------------
// Launch sequence (graph-capturable: kernel launches only)
// ---------------------------------------------------------------------------
extern "C" void kernel_launch(void* const* d_in, const int* in_sizes, int n_in,
                              void* d_out, int out_size)
{
    const float* hs   = (const float*)d_in[0];
    const float* w_in = (const float*)d_in[1];
    const float* cw   = (const float*)d_in[2];
    const float* cb   = (const float*)d_in[3];
    const float* w_x  = (const float*)d_in[4];
    const float* w_dt = (const float*)d_in[5];
    const float* b_dt = (const float*)d_in[6];
    const float* alog = (const float*)d_in[7];
    const float* dpar = (const float*)d_in[8];
    const float* w_o  = (const float*)d_in[9];
    float* out = (float*)d_out;

    float *proj, *sp, *dtb, *xpp;
    __half *hs_f, *win_fh, *win_fl, *y_f, *wo_fh, *wo_fl;
    __nv_bfloat16 *u_h, *u_l, *wx_h, *wx_l, *sp_h, *sp_l, *wdt_h, *wdt_l;
    cudaGetSymbolAddress((void**)&proj,   g_proj);
    cudaGetSymbolAddress((void**)&sp,     g_sp);
    cudaGetSymbolAddress((void**)&dtb,    g_dt);
    cudaGetSymbolAddress((void**)&xpp,    g_xpp);
    cudaGetSymbolAddress((void**)&hs_f,   g_hs_f);
    cudaGetSymbolAddress((void**)&win_fh, g_win_fh); cudaGetSymbolAddress((void**)&win_fl, g_win_fl);
    cudaGetSymbolAddress((void**)&y_f,    g_y_f);
    cudaGetSymbolAddress((void**)&wo_fh,  g_wo_fh);  cudaGetSymbolAddress((void**)&wo_fl,  g_wo_fl);
    cudaGetSymbolAddress((void**)&u_h,    g_u_h);    cudaGetSymbolAddress((void**)&u_l,    g_u_l);
    cudaGetSymbolAddress((void**)&wx_h,   g_wx_h);   cudaGetSymbolAddress((void**)&wx_l,   g_wx_l);
    cudaGetSymbolAddress((void**)&sp_h,   g_sp_h);   cudaGetSymbolAddress((void**)&sp_l,   g_sp_l);
    cudaGetSymbolAddress((void**)&wdt_h,  g_wdt_h);  cudaGetSymbolAddress((void**)&wdt_l,  g_wdt_l);

    cudaFuncSetAttribute(tgemm2h,          cudaFuncAttributeMaxDynamicSharedMemorySize, T2_SMEM);
    cudaFuncSetAttribute(tgemm4<0, true>,  cudaFuncAttributeMaxDynamicSharedMemorySize, T4_SMEM);
    cudaFuncSetAttribute(tgemm4<1, false>, cudaFuncAttributeMaxDynamicSharedMemorySize, T4_SMEM);

    // 0) conversions (1 launch)
    cvt_all<<<(CVT_N4 + 255) / 256, 256>>>(
        hs, hs_f, w_in, win_fh, win_fl, w_x, wx_h, wx_l,
        w_dt, wdt_h, wdt_l, w_o, wo_fh, wo_fl);

    // 1) in_proj (fp16 2-term): proj[2048, 8192] = hs @ w_in^T
    tgemm2h<<<dim3(P2D / 64, BL / 128), 128, T2_SMEM>>>(
        hs_f, HDIM, win_fh, win_fl, HDIM, proj, P2D, HDIM);

    // 2) conv + silu -> u (bf16 hi/lo)
    conv_silu_kernel<<<(BL / 4 * DDIM) / 256, 256>>>(proj, cw, cb, u_h, u_l);

    // 3) x_proj (bf16 3-term, split-K): partials[8][2048, 160] = u @ w_x^T
    tgemm4<0, true><<<dim3(3, BL / 128, XP_SPLIT), 128, T4_SMEM>>>(
        u_h, u_l, DDIM, wx_h, wx_l, DDIM, xpp, SP_W, SP_W, XP_KLEN,
        nullptr, (size_t)BL * SP_W);

    // 3b) reduce partials -> sp (fp32) + sp hi/lo (bf16)
    xp_reduce<<<(BL * SP_W / 4 + 255) / 256, 256>>>(xpp, sp, sp_h, sp_l);

    // 4) dt_proj (bf16 3-term) + bias + softplus
    tgemm4<1, false><<<dim3(DDIM / 64, BL / 128, 1), 128, T4_SMEM>>>(
        sp_h, sp_l, SP_W, wdt_h, wdt_l, RRANK, dtb, DDIM, DDIM, RRANK, b_dt, 0);

    // 5) selective scan + D-skip + gate -> y (fp16)
    scan_kernel<<<dim3(DDIM / 16, BSZ), 256>>>(dtb, u_h, u_l, sp, alog, dpar, proj, y_f);

    // 6) out_proj (fp16 2-term): out[2048, 2048] = y @ w_o^T
    tgemm2h<<<dim3(HDIM / 64, BL / 128), 128, T2_SMEM>>>(
        y_f, DDIM, wo_fh, wo_fl, DDIM, out, HDIM, DDIM);
}

// round 10
// speedup vs baseline: 1.7714x; 1.3244x over previous
#include <cuda_runtime.h>
#include <cuda_bf16.h>
#include <cuda_fp16.h>
#include <math.h>
#include <stdint.h>

// Problem constants (fixed by setup_inputs)
#define BSZ    2
#define LSEQ   1024
#define HDIM   2048
#define DDIM   4096
#define NSTATE 16
#define RRANK  128
#define KCONV  4
#define BL     (BSZ * LSEQ)          // 2048 rows
#define P2D    (2 * DDIM)            // 8192
#define SP_W   (RRANK + 2 * NSTATE)  // 160
#define XP_SPLIT 8
#define XP_KLEN  (DDIM / XP_SPLIT)   // 512

// ---------------------------------------------------------------------------
// Scratch: static device globals (no cudaMalloc allowed)
// ---------------------------------------------------------------------------
__device__ float g_proj[(size_t)BL * P2D];
__device__ float g_sp  [(size_t)BL * SP_W];
__device__ float g_dt  [(size_t)BL * DDIM];
__device__ float g_xpp [(size_t)XP_SPLIT * BL * SP_W];

// fp16 operands for in_proj / out_proj (pure fp16 1-term)
__device__ __half g_hs_f [(size_t)BL * HDIM];
__device__ __half g_win_f[(size_t)P2D * HDIM];
__device__ __half g_y_f  [(size_t)BL * DDIM];
__device__ __half g_wo_f [(size_t)HDIM * DDIM];

// bf16 hi/lo operands for x_proj / dt_proj (3-term scheme, precision path)
__device__ __nv_bfloat16 g_u_h[(size_t)BL * DDIM],   g_u_l[(size_t)BL * DDIM];
__device__ __nv_bfloat16 g_wx_h[(size_t)SP_W * DDIM], g_wx_l[(size_t)SP_W * DDIM];
__device__ __nv_bfloat16 g_sp_h[(size_t)BL * SP_W],  g_sp_l[(size_t)BL * SP_W];
__device__ __nv_bfloat16 g_wdt_h[(size_t)DDIM * RRANK], g_wdt_l[(size_t)DDIM * RRANK];

__device__ __forceinline__ float softplusf(float x) {
    return (x > 20.f) ? x : log1pf(__expf(x));
}
__device__ __forceinline__ float siluf(float x) {
    return x / (1.f + __expf(-x));
}

// ---------------------------------------------------------------------------
// PTX helpers
// ---------------------------------------------------------------------------
__device__ __forceinline__ uint32_t smem_u32(const void* p) {
    uint32_t a;
    asm("{ .reg .u64 t; cvta.to.shared.u64 t, %1; cvt.u32.u64 %0, t; }" : "=r"(a) : "l"(p));
    return a;
}
__device__ __forceinline__ void cpa16(uint32_t dst, const void* src, int sz) {
    asm volatile("cp.async.cg.shared.global [%0], [%1], 16, %2;"
                 :: "r"(dst), "l"(src), "r"(sz) : "memory");
}
__device__ __forceinline__ void cpa16f(uint32_t dst, const void* src) {
    asm volatile("cp.async.cg.shared.global [%0], [%1], 16;"
                 :: "r"(dst), "l"(src) : "memory");
}
__device__ __forceinline__ void cpa_commit() {
    asm volatile("cp.async.commit_group;" ::: "memory");
}
template <int N>
__device__ __forceinline__ void cpa_wait() {
    asm volatile("cp.async.wait_group %0;" :: "n"(N) : "memory");
}
__device__ __forceinline__ void ldsm_x4(uint32_t* r, uint32_t addr) {
    asm volatile("ldmatrix.sync.aligned.m8n8.x4.shared.b16 {%0,%1,%2,%3}, [%4];"
                 : "=r"(r[0]), "=r"(r[1]), "=r"(r[2]), "=r"(r[3]) : "r"(addr));
}
__device__ __forceinline__ void mma_bf16(float* c, const uint32_t* a, const uint32_t* b) {
    asm volatile(
        "mma.sync.aligned.m16n8k16.row.col.f32.bf16.bf16.f32 "
        "{%0,%1,%2,%3}, {%4,%5,%6,%7}, {%8,%9}, {%0,%1,%2,%3};"
        : "+f"(c[0]), "+f"(c[1]), "+f"(c[2]), "+f"(c[3])
        : "r"(a[0]), "r"(a[1]), "r"(a[2]), "r"(a[3]), "r"(b[0]), "r"(b[1]));
}
__device__ __forceinline__ void mma_f16(float* c, const uint32_t* a, const uint32_t* b) {
    asm volatile(
        "mma.sync.aligned.m16n8k16.row.col.f32.f16.f16.f32 "
        "{%0,%1,%2,%3}, {%4,%5,%6,%7}, {%8,%9}, {%0,%1,%2,%3};"
        : "+f"(c[0]), "+f"(c[1]), "+f"(c[2]), "+f"(c[3])
        : "r"(a[0]), "r"(a[1]), "r"(a[2]), "r"(a[3]), "r"(b[0]), "r"(b[1]));
}

// ---------------------------------------------------------------------------
// Merged conversions (1 launch):
//   hs -> fp16, w_in -> fp16, w_x -> bf16 hi/lo, w_dt -> bf16 hi/lo, w_o -> fp16
// ---------------------------------------------------------------------------
#define CVT_N0 (BL * HDIM / 4)
#define CVT_N1 (CVT_N0 + P2D * HDIM / 4)
#define CVT_N2 (CVT_N1 + SP_W * DDIM / 4)
#define CVT_N3 (CVT_N2 + DDIM * RRANK / 4)
#define CVT_N4 (CVT_N3 + HDIM * DDIM / 4)

__device__ __forceinline__ void cvt_bf16_hl(const float* __restrict__ x,
                                            __nv_bfloat16* __restrict__ h,
                                            __nv_bfloat16* __restrict__ l, int i)
{
    float4 v = ((const float4*)x)[i];
    __nv_bfloat162 h0 = __floats2bfloat162_rn(v.x, v.y);
    __nv_bfloat162 h1 = __floats2bfloat162_rn(v.z, v.w);
    __nv_bfloat162 l0 = __floats2bfloat162_rn(v.x - __low2float(h0), v.y - __high2float(h0));
    __nv_bfloat162 l1 = __floats2bfloat162_rn(v.z - __low2float(h1), v.w - __high2float(h1));
    ((__nv_bfloat162*)h)[2 * i]     = h0;
    ((__nv_bfloat162*)h)[2 * i + 1] = h1;
    ((__nv_bfloat162*)l)[2 * i]     = l0;
    ((__nv_bfloat162*)l)[2 * i + 1] = l1;
}
__device__ __forceinline__ void cvt_f16_s(const float* __restrict__ x,
                                          __half* __restrict__ h, int i)
{
    float4 v = ((const float4*)x)[i];
    ((__half2*)h)[2 * i]     = __floats2half2_rn(v.x, v.y);
    ((__half2*)h)[2 * i + 1] = __floats2half2_rn(v.z, v.w);
}

__global__ void cvt_all(const float* hs,  __half* hsf,
                        const float* win, __half* winf,
                        const float* wx,  __nv_bfloat16* wxh, __nv_bfloat16* wxl,
                        const float* wdt, __nv_bfloat16* wdh, __nv_bfloat16* wdl,
                        const float* wo,  __half* wof)
{
    int i = blockIdx.x * blockDim.x + threadIdx.x;
    if (i < CVT_N0)      cvt_f16_s (hs,  hsf,  i);
    else if (i < CVT_N1) cvt_f16_s (win, winf, i - CVT_N0);
    else if (i < CVT_N2) cvt_bf16_hl(wx, wxh, wxl,  i - CVT_N1);
    else if (i < CVT_N3) cvt_bf16_hl(wdt, wdh, wdl, i - CVT_N2);
    else if (i < CVT_N4) cvt_f16_s (wo,  wof,  i - CVT_N3);
}

// ===========================================================================
// Shared tile loaders (2-byte element types; 64B rows, SW64-style swizzle)
// ===========================================================================
template <typename T>
__device__ __forceinline__ void load128(const T* __restrict__ src, int ld,
                                        int row0, int k0, uint32_t dstbase, int tid)
{
#pragma unroll
    for (int i = 0; i < 4; i++) {
        const int u   = tid + i * 128;        // 0..511
        const int row = u >> 2;               // 0..127
        const int s   = u & 3;
        const uint32_t off = (uint32_t)(row * 64 + ((s * 16) ^ ((row & 6) << 3)));
        cpa16f(dstbase + off, src + (size_t)(row0 + row) * ld + k0 + s * 8);
    }
}
template <typename T, bool GUARD>
__device__ __forceinline__ void load64(const T* __restrict__ src, int ld,
                                       int row0, int k0, uint32_t dstbase,
                                       int tid, int nrows)
{
#pragma unroll
    for (int i = 0; i < 2; i++) {
        const int u   = tid + i * 128;        // 0..255
        const int row = u >> 2;               // 0..63
        const int s   = u & 3;
        const uint32_t off = (uint32_t)(row * 64 + ((s * 16) ^ ((row & 6) << 3)));
        if (GUARD) {
            const int ok = (row0 + row) < nrows;
            const void* p = src + (size_t)(row0 + (ok ? row : 0)) * ld + k0 + s * 8;
            cpa16(dstbase + off, p, ok ? 16 : 0);
        } else {
            cpa16f(dstbase + off, src + (size_t)(row0 + row) * ld + k0 + s * 8);
        }
    }
}

// ===========================================================================
// Pure fp16 1-term GEMM (in_proj / out_proj): C = A * B^T, fp32 acc.
// CTA tile 128x64, 4 warps, BK=32, 3 stages x 12KB = 36KB -> 4 CTAs/SM.
// ===========================================================================
#define T1_A      8192               // 128 rows x 64B
#define T1_B      4096               // 64 rows x 64B
#define T1_STAGE  (T1_A + T1_B)      // 12KB
#define T1_NSTG   3
#define T1_SMEM   (T1_NSTG * T1_STAGE)   // 36KB

__global__ void __launch_bounds__(128, 4)
tgemm1h(const __half* __restrict__ A, int lda,
        const __half* __restrict__ B, int ldb,
        float* __restrict__ C, int ldc, int klen)
{
    extern __shared__ __align__(1024) char smem[];
    const uint32_t sbase = smem_u32(smem);

    const int tid  = threadIdx.x;
    const int wid  = tid >> 5;
    const int lane = tid & 31;
    const int m0   = blockIdx.y * 128;
    const int n0   = blockIdx.x * 64;
    const int wm   = wid >> 1;
    const int wn   = wid & 1;

    const uint32_t khiA = (uint32_t)((lane >> 4) * 16);
    const uint32_t khiB = (uint32_t)(((lane >> 3) & 1) * 16);
    uint32_t pA[4], xA[4], pB[2], xB[2];
#pragma unroll
    for (int i = 0; i < 4; i++) {
        const int r = wm * 64 + i * 16 + (lane & 15);
        pA[i] = (uint32_t)(r * 64);
        xA[i] = (uint32_t)((r & 6) << 3);
    }
#pragma unroll
    for (int j2 = 0; j2 < 2; j2++) {
        const int r = wn * 32 + j2 * 16 + ((lane >> 4) << 3) + (lane & 7);
        pB[j2] = (uint32_t)(r * 64);
        xB[j2] = (uint32_t)((r & 6) << 3);
    }

    float acc[4][4][4];
#pragma unroll
    for (int i = 0; i < 4; i++)
#pragma unroll
        for (int j = 0; j < 4; j++)
#pragma unroll
            for (int r = 0; r < 4; r++) acc[i][j][r] = 0.f;

    const int nch = klen >> 5;

#pragma unroll
    for (int s = 0; s < T1_NSTG - 1; s++) {
        if (s < nch) {
            uint32_t st = sbase + s * T1_STAGE;
            const int k0 = s << 5;
            load128(A, lda, m0, k0, st, tid);
            load64<__half, false>(B, ldb, n0, k0, st + T1_A, tid, 0);
        }
        cpa_commit();
    }

    for (int c = 0; c < nch; c++) {
        cpa_wait<T1_NSTG - 2>();
        __syncthreads();

        const int cp = c + T1_NSTG - 1;
        if (cp < nch) {
            uint32_t st = sbase + (cp % T1_NSTG) * T1_STAGE;
            const int k0 = cp << 5;
            load128(A, lda, m0, k0, st, tid);
            load64<__half, false>(B, ldb, n0, k0, st + T1_A, tid, 0);
        }
        cpa_commit();

        const uint32_t aS = sbase + (c % T1_NSTG) * T1_STAGE;
        const uint32_t bS = aS + T1_A;

#pragma unroll
        for (int ks = 0; ks < 2; ks++) {
            const uint32_t kA = (uint32_t)(ks * 32) + khiA;
            const uint32_t kB = (uint32_t)(ks * 32) + khiB;
            uint32_t ah[4][4];
#pragma unroll
            for (int i = 0; i < 4; i++)
                ldsm_x4(ah[i], aS + pA[i] + (kA ^ xA[i]));
            uint32_t bh[2][4];
#pragma unroll
            for (int j2 = 0; j2 < 2; j2++)
                ldsm_x4(bh[j2], bS + pB[j2] + (kB ^ xB[j2]));
#pragma unroll
            for (int j = 0; j < 4; j++)
#pragma unroll
                for (int i = 0; i < 4; i++)
                    mma_f16(acc[i][j], ah[i], &bh[j >> 1][(j & 1) * 2]);
        }
    }

    const int qr = lane >> 2;
    const int qc = (lane & 3) * 2;
#pragma unroll
    for (int i = 0; i < 4; i++) {
        const int r0 = m0 + wm * 64 + i * 16 + qr;
#pragma unroll
        for (int j = 0; j < 4; j++) {
            const int nn = n0 + wn * 32 + j * 8 + qc;
            *(float2*)(C + (size_t)r0 * ldc + nn)       = make_float2(acc[i][j][0], acc[i][j][1]);
            *(float2*)(C + (size_t)(r0 + 8) * ldc + nn) = make_float2(acc[i][j][2], acc[i][j][3]);
        }
    }
}

// ===========================================================================
// bf16 3-term GEMM (x_proj / dt_proj): R7-winning structure, 3 CTAs/SM.
// C = Ah*Bh + Ah*Bl + Al*Bh.  EPI==1: softplus(C + bias[n]).
// ===========================================================================
#define T4_A      8192
#define T4_B      4096
#define T4_STAGE  (2 * T4_A + 2 * T4_B)      // 24KB
#define T4_NSTG   3
#define T4_SMEM   (T4_NSTG * T4_STAGE)       // 72KB

template <int EPI, bool GUARD>
__global__ void __launch_bounds__(128, 3)
tgemm4(const __nv_bfloat16* __restrict__ Ah, const __nv_bfloat16* __restrict__ Al, int lda,
       const __nv_bfloat16* __restrict__ Bh, const __nv_bfloat16* __restrict__ Bl, int ldb,
       float* __restrict__ C, int ldc, int Nc, int klen,
       const float* __restrict__ bias, size_t partStride)
{
    extern __shared__ __align__(1024) char smem[];
    const uint32_t sbase = smem_u32(smem);

    const int tid  = threadIdx.x;
    const int wid  = tid >> 5;
    const int lane = tid & 31;
    const int m0   = blockIdx.y * 128;
    const int n0   = blockIdx.x * 64;
    const int kb   = blockIdx.z * klen;
    C += (size_t)blockIdx.z * partStride;
    const int wm   = wid >> 1;
    const int wn   = wid & 1;

    const uint32_t khiA = (uint32_t)((lane >> 4) * 16);
    const uint32_t khiB = (uint32_t)(((lane >> 3) & 1) * 16);
    uint32_t pA[4], xA[4], pB[2], xB[2];
#pragma unroll
    for (int i = 0; i < 4; i++) {
        const int r = wm * 64 + i * 16 + (lane & 15);
        pA[i] = (uint32_t)(r * 64);
        xA[i] = (uint32_t)((r & 6) << 3);
    }
#pragma unroll
    for (int j2 = 0; j2 < 2; j2++) {
        const int r = wn * 32 + j2 * 16 + ((lane >> 4) << 3) + (lane & 7);
        pB[j2] = (uint32_t)(r * 64);
        xB[j2] = (uint32_t)((r & 6) << 3);
    }

    float acc[4][4][4];
#pragma unroll
    for (int i = 0; i < 4; i++)
#pragma unroll
        for (int j = 0; j < 4; j++)
#pragma unroll
            for (int r = 0; r < 4; r++) acc[i][j][r] = 0.f;

    const int nch = klen >> 5;

#pragma unroll
    for (int s = 0; s < T4_NSTG - 1; s++) {
        if (s < nch) {
            uint32_t st = sbase + s * T4_STAGE;
            const int k0 = kb + (s << 5);
            load128(Ah, lda, m0, k0, st,        tid);
            load128(Al, lda, m0, k0, st + T4_A, tid);
            load64<__nv_bfloat16, GUARD>(Bh, ldb, n0, k0, st + 2 * T4_A,        tid, Nc);
            load64<__nv_bfloat16, GUARD>(Bl, ldb, n0, k0, st + 2 * T4_A + T4_B, tid, Nc);
        }
        cpa_commit();
    }

    for (int c = 0; c < nch; c++) {
        cpa_wait<T4_NSTG - 2>();
        __syncthreads();

        const int cp = c + T4_NSTG - 1;
        if (cp < nch) {
            uint32_t st = sbase + (cp % T4_NSTG) * T4_STAGE;
            const int k0 = kb + (cp << 5);
            load128(Ah, lda, m0, k0, st,        tid);
            load128(Al, lda, m0, k0, st + T4_A, tid);
            load64<__nv_bfloat16, GUARD>(Bh, ldb, n0, k0, st + 2 * T4_A,        tid, Nc);
            load64<__nv_bfloat16, GUARD>(Bl, ldb, n0, k0, st + 2 * T4_A + T4_B, tid, Nc);
        }
        cpa_commit();

        const uint32_t aH = sbase + (c % T4_NSTG) * T4_STAGE;
        const uint32_t aL = aH + T4_A;
        const uint32_t bH = aH + 2 * T4_A;
        const uint32_t bL = bH + T4_B;

#pragma unroll
        for (int ks = 0; ks < 2; ks++) {
            const uint32_t kA = (uint32_t)(ks * 32) + khiA;
            const uint32_t kB = (uint32_t)(ks * 32) + khiB;
            uint32_t ah[4][4], al[4][4];
#pragma unroll
            for (int i = 0; i < 4; i++) {
                ldsm_x4(ah[i], aH + pA[i] + (kA ^ xA[i]));
                ldsm_x4(al[i], aL + pA[i] + (kA ^ xA[i]));
            }
            uint32_t bh[2][4], bl[2][4];
#pragma unroll
            for (int j2 = 0; j2 < 2; j2++) {
                ldsm_x4(bh[j2], bH + pB[j2] + (kB ^ xB[j2]));
                ldsm_x4(bl[j2], bL + pB[j2] + (kB ^ xB[j2]));
            }
#pragma unroll
            for (int j = 0; j < 4; j++)
#pragma unroll
                for (int i = 0; i < 4; i++)
                    mma_bf16(acc[i][j], ah[i], &bh[j >> 1][(j & 1) * 2]);
#pragma unroll
            for (int j = 0; j < 4; j++)
#pragma unroll
                for (int i = 0; i < 4; i++)
                    mma_bf16(acc[i][j], ah[i], &bl[j >> 1][(j & 1) * 2]);
#pragma unroll
            for (int j = 0; j < 4; j++)
#pragma unroll
                for (int i = 0; i < 4; i++)
                    mma_bf16(acc[i][j], al[i], &bh[j >> 1][(j & 1) * 2]);
        }
    }

    const int qr = lane >> 2;
    const int qc = (lane & 3) * 2;
#pragma unroll
    for (int i = 0; i < 4; i++) {
        const int r0 = m0 + wm * 64 + i * 16 + qr;
#pragma unroll
        for (int j = 0; j < 4; j++) {
            const int nn = n0 + wn * 32 + j * 8 + qc;
            if (!GUARD || nn < Nc) {
                float2 v0 = make_float2(acc[i][j][0], acc[i][j][1]);
                float2 v1 = make_float2(acc[i][j][2], acc[i][j][3]);
                if (EPI == 1) {
                    const float b0 = bias[nn], b1 = bias[nn + 1];
                    v0.x = softplusf(v0.x + b0); v0.y = softplusf(v0.y + b1);
                    v1.x = softplusf(v1.x + b0); v1.y = softplusf(v1.y + b1);
                }
                *(float2*)(C + (size_t)r0 * ldc + nn)       = v0;
                *(float2*)(C + (size_t)(r0 + 8) * ldc + nn) = v1;
            }
        }
    }
}

// ---------------------------------------------------------------------------
// split-K reduce for x_proj: sp = sum(partials); also emit bf16 hi/lo
// ---------------------------------------------------------------------------
__global__ void xp_reduce(const float* __restrict__ part,
                          float* __restrict__ sp,
                          __nv_bfloat16* __restrict__ sph,
                          __nv_bfloat16* __restrict__ spl)
{
    const int n4 = BL * SP_W / 4;
    int i = blockIdx.x * blockDim.x + threadIdx.x;
    if (i >= n4) return;
    float4 a = ((const float4*)part)[i];
#pragma unroll
    for (int p = 1; p < XP_SPLIT; p++) {
        float4 b = ((const float4*)part)[i + (size_t)p * n4];
        a.x += b.x; a.y += b.y; a.z += b.z; a.w += b.w;
    }
    ((float4*)sp)[i] = a;
    __nv_bfloat162 h0 = __floats2bfloat162_rn(a.x, a.y);
    __nv_bfloat162 h1 = __floats2bfloat162_rn(a.z, a.w);
    __nv_bfloat162 l0 = __floats2bfloat162_rn(a.x - __low2float(h0), a.y - __high2float(h0));
    __nv_bfloat162 l1 = __floats2bfloat162_rn(a.z - __low2float(h1), a.w - __high2float(h1));
    ((__nv_bfloat162*)sph)[2 * i]     = h0;
    ((__nv_bfloat162*)sph)[2 * i + 1] = h1;
    ((__nv_bfloat162*)spl)[2 * i]     = l0;
    ((__nv_bfloat162*)spl)[2 * i + 1] = l1;
}

// ---------------------------------------------------------------------------
// Depthwise causal conv1d (K=4) + bias + silu -> u bf16 hi/lo
// ---------------------------------------------------------------------------
__global__ void conv_silu_kernel(const float* __restrict__ proj,
                                 const float* __restrict__ cw,
                                 const float* __restrict__ cb,
                                 __nv_bfloat16* __restrict__ uh,
                                 __nv_bfloat16* __restrict__ ul)
{
    const int t = blockIdx.x * blockDim.x + threadIdx.x;
    if (t >= (BL / 4) * DDIM) return;
    const int d   = t & (DDIM - 1);
    const int q   = t >> 12;
    const int bl0 = q * 4;
    const int l0  = bl0 & (LSEQ - 1);

    const float4 w = *(const float4*)(cw + d * 4);
    const float  b = cb[d];
    const float* base = proj + (size_t)bl0 * P2D + d;
    const bool   lz = (l0 == 0);

    float x[7];
#pragma unroll
    for (int i = 0; i < 7; i++)
        x[i] = (!lz || i >= 3) ? base[(i - 3) * P2D] : 0.f;

#pragma unroll
    for (int k = 0; k < 4; k++) {
        float acc = b;
        acc = fmaf(w.x, x[k],     acc);
        acc = fmaf(w.y, x[k + 1], acc);
        acc = fmaf(w.z, x[k + 2], acc);
        acc = fmaf(w.w, x[k + 3], acc);
        const float v = siluf(acc);
        const __nv_bfloat16 h = __float2bfloat16(v);
        const size_t off = (size_t)(bl0 + k) * DDIM + d;
        uh[off] = h;
        ul[off] = __float2bfloat16(v - __bfloat162float(h));
    }
}

// ---------------------------------------------------------------------------
// Selective scan -> y single fp16 (for fp16 out_proj)
// ---------------------------------------------------------------------------
__global__ void __launch_bounds__(256)
scan_kernel(const float* __restrict__ dtg,
            const __nv_bfloat16* __restrict__ uhg,
            const __nv_bfloat16* __restrict__ ulg,
            const float* __restrict__ spg,
            const float* __restrict__ Alog,
            const float* __restrict__ Dp,
            const float* __restrict__ proj,
            __half* __restrict__ yf)
{
    const int b   = blockIdx.y;
    const int d0  = blockIdx.x * 16;
    const int t   = threadIdx.x;
    const int seq = t >> 4;
    const int n   = t & 15;
    const int d   = d0 + seq;

    __shared__ float sdt[64][16];
    __shared__ float su [64][16];
    __shared__ float sB [64][16];
    __shared__ float sC [64][16];
    __shared__ float sy [64][16];

    const float a = -__expf(Alog[d * NSTATE + n]);
    float s = 0.f;

    const int i16 = t >> 4, j16 = t & 15;
    const int i32 = t >> 5, j32 = t & 31;

    for (int l0 = 0; l0 < LSEQ; l0 += 64) {
        const int bl0 = b * LSEQ + l0;
#pragma unroll
        for (int r = 0; r < 4; r++) {
            const int ii = i16 + r * 16;
            const size_t off = (size_t)(bl0 + ii) * DDIM + d0 + j16;
            sdt[ii][j16] = dtg[off];
            su [ii][j16] = __bfloat162float(uhg[off]) + __bfloat162float(ulg[off]);
        }
#pragma unroll
        for (int r = 0; r < 8; r++) {
            const int ii = i32 + r * 8;
            const float v = spg[(size_t)(bl0 + ii) * SP_W + RRANK + j32];
            if (j32 < 16) sB[ii][j32] = v;
            else          sC[ii][j32 - 16] = v;
        }
        __syncthreads();

#pragma unroll 4
        for (int il = 0; il < 64; il++) {
            const float dtv = sdt[il][seq];
            const float dA  = __expf(a * dtv);
            const float dBu = dtv * sB[il][n] * su[il][seq];
            s = fmaf(dA, s, dBu);
            float p = s * sC[il][n];
            p += __shfl_xor_sync(0xffffffffu, p, 8);
            p += __shfl_xor_sync(0xffffffffu, p, 4);
            p += __shfl_xor_sync(0xffffffffu, p, 2);
            p += __shfl_xor_sync(0xffffffffu, p, 1);
            if (n == 0) sy[il][seq] = p;
        }
        __syncthreads();

#pragma unroll
        for (int r = 0; r < 4; r++) {
            const int ii = i16 + r * 16;
            const float yy = sy[ii][j16];
            const float uu = su[ii][j16];
            const float g  = proj[(size_t)(bl0 + ii) * P2D + DDIM + d0 + j16];
            const float yv = fmaf(uu, Dp[d0 + j16], yy) * siluf(g);
            yf[(size_t)(bl0 + ii) * DDIM + d0 + j16] = __float2half_rn(yv);
        }
        __syncthreads();
    }
}

// ---------------------------------------------------------------------------
// Launch sequence (graph-capturable: kernel launches only)
// ---------------------------------------------------------------------------
extern "C" void kernel_launch(void* const* d_in, const int* in_sizes, int n_in,
                              void* d_out, int out_size)
{
    const float* hs   = (const float*)d_in[0];
    const float* w_in = (const float*)d_in[1];
    const float* cw   = (const float*)d_in[2];
    const float* cb   = (const float*)d_in[3];
    const float* w_x  = (const float*)d_in[4];
    const float* w_dt = (const float*)d_in[5];
    const float* b_dt = (const float*)d_in[6];
    const float* alog = (const float*)d_in[7];
    const float* dpar = (const float*)d_in[8];
    const float* w_o  = (const float*)d_in[9];
    float* out = (float*)d_out;

    float *proj, *sp, *dtb, *xpp;
    __half *hs_f, *win_f, *y_f, *wo_f;
    __nv_bfloat16 *u_h, *u_l, *wx_h, *wx_l, *sp_h, *sp_l, *wdt_h, *wdt_l;
    cudaGetSymbolAddress((void**)&proj,  g_proj);
    cudaGetSymbolAddress((void**)&sp,    g_sp);
    cudaGetSymbolAddress((void**)&dtb,   g_dt);
    cudaGetSymbolAddress((void**)&xpp,   g_xpp);
    cudaGetSymbolAddress((void**)&hs_f,  g_hs_f);
    cudaGetSymbolAddress((void**)&win_f, g_win_f);
    cudaGetSymbolAddress((void**)&y_f,   g_y_f);
    cudaGetSymbolAddress((void**)&wo_f,  g_wo_f);
    cudaGetSymbolAddress((void**)&u_h,   g_u_h);   cudaGetSymbolAddress((void**)&u_l,   g_u_l);
    cudaGetSymbolAddress((void**)&wx_h,  g_wx_h);  cudaGetSymbolAddress((void**)&wx_l,  g_wx_l);
    cudaGetSymbolAddress((void**)&sp_h,  g_sp_h);  cudaGetSymbolAddress((void**)&sp_l,  g_sp_l);
    cudaGetSymbolAddress((void**)&wdt_h, g_wdt_h); cudaGetSymbolAddress((void**)&wdt_l, g_wdt_l);

    cudaFuncSetAttribute(tgemm1h,          cudaFuncAttributeMaxDynamicSharedMemorySize, T1_SMEM);
    cudaFuncSetAttribute(tgemm4<0, true>,  cudaFuncAttributeMaxDynamicSharedMemorySize, T4_SMEM);
    cudaFuncSetAttribute(tgemm4<1, false>, cudaFuncAttributeMaxDynamicSharedMemorySize, T4_SMEM);

    // 0) conversions (1 launch)
    cvt_all<<<(CVT_N4 + 255) / 256, 256>>>(
        hs, hs_f, w_in, win_f, w_x, wx_h, wx_l, w_dt, wdt_h, wdt_l, w_o, wo_f);

    // 1) in_proj (pure fp16): proj[2048, 8192] = hs @ w_in^T
    tgemm1h<<<dim3(P2D / 64, BL / 128), 128, T1_SMEM>>>(
        hs_f, HDIM, win_f, HDIM, proj, P2D, HDIM);

    // 2) conv + silu -> u (bf16 hi/lo)
    conv_silu_kernel<<<(BL / 4 * DDIM) / 256, 256>>>(proj, cw, cb, u_h, u_l);

    // 3) x_proj (bf16 3-term, split-K): partials[8][2048, 160] = u @ w_x^T
    tgemm4<0, true><<<dim3(3, BL / 128, XP_SPLIT), 128, T4_SMEM>>>(
        u_h, u_l, DDIM, wx_h, wx_l, DDIM, xpp, SP_W, SP_W, XP_KLEN,
        nullptr, (size_t)BL * SP_W);

    // 3b) reduce partials -> sp (fp32) + sp hi/lo (bf16)
    xp_reduce<<<(BL * SP_W / 4 + 255) / 256, 256>>>(xpp, sp, sp_h, sp_l);

    // 4) dt_proj (bf16 3-term) + bias + softplus
    tgemm4<1, false><<<dim3(DDIM / 64, BL / 128, 1), 128, T4_SMEM>>>(
        sp_h, sp_l, SP_W, wdt_h, wdt_l, RRANK, dtb, DDIM, DDIM, RRANK, b_dt, 0);

    // 5) selective scan + D-skip + gate -> y (fp16)
    scan_kernel<<<dim3(DDIM / 16, BSZ), 256>>>(dtb, u_h, u_l, sp, alog, dpar, proj, y_f);

    // 6) out_proj (pure fp16): out[2048, 2048] = y @ w_o^T
    tgemm1h<<<dim3(HDIM / 64, BL / 128), 128, T1_SMEM>>>(
        y_f, DDIM, wo_f, DDIM, out, HDIM, DDIM);
}